// round 7
// baseline (speedup 1.0000x reference)
#include <cuda_runtime.h>
#include <cuda_bf16.h>
#include <math.h>

#define BB 8
#define TT 256
#define UU 65
#define UL 64
#define VV 1024
#define ND 320            // stored diagonals: t+u in [0, 319]
#define ST 66             // diag row stride (floats), even => 8B-aligned float2
#define NEG_BIG (-1e30f)
#define LOG2E 1.4426950408889634f
#define LN2F  0.6931471805599453f

__device__ __align__(16) float g_blankD[BB * ND * ST];  // [b][t+u][u] = lp_blank(t,u)
__device__ __align__(16) float g_labelD[BB * ND * ST];  // [b][t+u][u] = lp_label(t,u), u<64
__device__ int   g_cntD[BB * ND];                        // cells published per (b, t+u)
__device__ float g_ll[BB];
__device__ int   g_done;

__device__ __forceinline__ float warpMax(float v) {
#pragma unroll
    for (int o = 16; o > 0; o >>= 1) v = fmaxf(v, __shfl_xor_sync(0xffffffffu, v, o));
    return v;
}
__device__ __forceinline__ float warpSum(float v) {
#pragma unroll
    for (int o = 16; o > 0; o >>= 1) v += __shfl_xor_sync(0xffffffffu, v, o);
    return v;
}
// log-add-exp in log2 domain
__device__ __forceinline__ float lae2(float a, float b) {
    float m = fmaxf(a, b);
    float d = fminf(a, b) - m;
    float p, r;
    asm("ex2.approx.ftz.f32 %0, %1;" : "=f"(p) : "f"(d));
    float q = 1.f + p;
    asm("lg2.approx.ftz.f32 %0, %1;" : "=f"(r) : "f"(q));
    return m + r;
}

struct Ops { float bx, by, b64, lx, ly; };

__global__ void __launch_bounds__(256) rnnt_fused(const float* __restrict__ acts,
                                                  const int* __restrict__ labels,
                                                  const int* __restrict__ act_lens,
                                                  const int* __restrict__ label_lens,
                                                  float* __restrict__ out) {
    const int lane = threadIdx.x & 31;
    const int wid  = threadIdx.x >> 5;

    if (blockIdx.x >= 8) {
        // ===================== LSE producer (proven R6 body) =================
        const int row = (blockIdx.x - 8) * 8 + wid;     // b-row-major, as R6
        const int u  = row % UU;
        const int bt = row / UU;
        const int t  = bt % TT;
        const int b  = bt / TT;

        const float4* a4 = reinterpret_cast<const float4*>(acts + (size_t)row * VV);
        float4 v[8];
#pragma unroll
        for (int j = 0; j < 8; ++j) v[j] = a4[lane + 32 * j];

        float m = -INFINITY;
#pragma unroll
        for (int j = 0; j < 8; ++j)
            m = fmaxf(m, fmaxf(fmaxf(v[j].x, v[j].y), fmaxf(v[j].z, v[j].w)));
        m = warpMax(m);

        float s = 0.f;
#pragma unroll
        for (int j = 0; j < 8; ++j)
            s += __expf(v[j].x - m) + __expf(v[j].y - m) + __expf(v[j].z - m) + __expf(v[j].w - m);
        s = warpSum(s);
        const float lse = m + __logf(s);

        float lv = 0.f;
        if (u < UL) {
            const int lab = labels[b * UL + u];
            const int q = lab >> 2, c = lab & 3, jj = q >> 5;
            float cand = 0.f;
#pragma unroll
            for (int j = 0; j < 8; ++j) {
                if (j == jj) {
                    float4 f = v[j];
                    cand = (c == 0) ? f.x : (c == 1) ? f.y : (c == 2) ? f.z : f.w;
                }
            }
            lv = __shfl_sync(0xffffffffu, cand, q & 31);
        }
        if (lane == 0) {
            const size_t base = ((size_t)b * ND + (t + u)) * ST + u;
            asm volatile("st.global.cg.f32 [%0], %1;"
                         :: "l"(g_blankD + base), "f"(v[0].x - lse) : "memory");
            if (u < UL)
                asm volatile("st.global.cg.f32 [%0], %1;"
                             :: "l"(g_labelD + base), "f"(lv - lse) : "memory");
            asm volatile("red.release.gpu.global.add.s32 [%0], 1;"
                         :: "l"(g_cntD + b * ND + t + u) : "memory");
        }
        return;
    }

    // ===================== ALPHA consumer: one warp per batch ================
    if (wid != 0) return;
    const int b = blockIdx.x;

    const int t_tgt = act_lens[b] - 1;
    const int u_tgt = label_lens[b];
    const int d_tgt = t_tgt + u_tgt;

    const float* BD  = g_blankD + (size_t)b * ND * ST;
    const float* LD2 = g_labelD + (size_t)b * ND * ST;
    const int*   CD  = g_cntD + b * ND;

    const int u0 = 2 * lane, u1 = u0 + 1;

    auto gateTo = [&](int lo, int hi) {
        for (int dd = lo; dd <= hi; ++dd) {
            const int ce = min(64, dd) - max(0, dd - (TT - 1)) + 1;
            int vv;
            for (;;) {
                asm volatile("ld.global.cg.s32 %0, [%1];" : "=r"(vv) : "l"(CD + dd));
                if (vv >= ce) break;
                __nanosleep(64);
            }
        }
    };
    auto loadOps = [&](int d) {
        const int dd = d - 1;
        const float* bp = BD  + (size_t)dd * ST;
        const float* lp = LD2 + (size_t)dd * ST;
        Ops o;
        asm volatile("ld.global.cg.v2.f32 {%0,%1}, [%2];" : "=f"(o.bx), "=f"(o.by) : "l"(bp + u0));
        asm volatile("ld.global.cg.v2.f32 {%0,%1}, [%2];" : "=f"(o.lx), "=f"(o.ly) : "l"(lp + u0));
        asm volatile("ld.global.cg.f32 %0, [%1];"         : "=f"(o.b64)            : "l"(bp + 64));
        return o;
    };

    float a0 = 0.f, a1 = 0.f, a2 = 0.f, tgt = 0.f;

    int gated = 9;
    gateTo(0, gated);
    Ops oA = loadOps(1);     // stored diag 0
    Ops oB = loadOps(2);     // stored diag 1

#pragma unroll 2
    for (int d = 1; d <= TT + UU - 2; ++d) {           // 1..319
        if (d + 1 > gated && gated < ND - 1) {          // prefetch needs dd = d+1
            const int hi = min(gated + 8, ND - 1);
            gateTo(gated + 1, hi);
            gated = hi;
        }
        Ops oC = (d <= TT + UU - 4) ? loadOps(d + 2) : oA;   // dummy after end

        // compute diag d from oA (loads issued 2 iters ago)
        const float l_m1 = __shfl_up_sync(0xffffffffu, oA.ly, 1);   // labelD[d-1][u0-1]
        const float l_63 = __shfl_sync(0xffffffffu, oA.ly, 31);     // labelD[d-1][63]
        float pm = __shfl_up_sync(0xffffffffu, a1, 1);
        pm = (lane == 0) ? NEG_BIG : pm;

        const int t0 = d - u0, t1 = t0 - 1, t2 = d - 64;

        const float bl0 = (t0 >= 1) ? oA.bx * LOG2E : NEG_BIG;
        const float n0  = lae2(a0 + bl0, pm + l_m1 * LOG2E);

        const float bl1 = (t1 >= 1) ? oA.by * LOG2E : NEG_BIG;
        const float n1  = lae2(a1 + bl1, a0 + oA.lx * LOG2E);

        const float bl2 = (t2 >= 1) ? oA.b64 * LOG2E : NEG_BIG;
        const float n2  = lae2(a2 + bl2, a1 + l_63 * LOG2E);

        a0 = (t0 >= 0 && t0 < TT) ? n0 : a0;
        a1 = (t1 >= 0 && t1 < TT) ? n1 : a1;
        a2 = (t2 >= 0 && t2 < TT) ? n2 : a2;

        const float pick = (u_tgt == u0) ? n0 : ((u_tgt == u1) ? n1 : n2);
        tgt = (d == d_tgt) ? pick : tgt;

        oA = oB; oB = oC;
    }

    gateTo(d_tgt, d_tgt);   // epilogue blank (usually already full)
    const int owner = (u_tgt >= 64) ? 31 : (u_tgt >> 1);
    const float av = __shfl_sync(0xffffffffu, tgt, owner);

    // reset this batch's counters for the next graph replay (all observed full)
    for (int k = lane; k < ND; k += 32)
        asm volatile("st.global.cg.s32 [%0], %1;" :: "l"(const_cast<int*>(CD) + k), "r"(0) : "memory");

    if (lane == 0) {
        float bl;
        asm volatile("ld.global.cg.f32 %0, [%1];" : "=f"(bl)
                     : "l"(BD + (size_t)d_tgt * ST + u_tgt));
        const float ll = (av + bl * LOG2E) * LN2F;
        asm volatile("st.global.cg.f32 [%0], %1;" :: "l"(g_ll + b), "f"(ll) : "memory");
        int old;
        asm volatile("atom.acq_rel.gpu.global.add.s32 %0, [%1], 1;"
                     : "=r"(old) : "l"(&g_done) : "memory");
        if (old == BB - 1) {               // last consumer: deterministic finalize
            float s = 0.f;
#pragma unroll
            for (int i = 0; i < BB; ++i) {
                float x;
                asm volatile("ld.global.cg.f32 %0, [%1];" : "=f"(x) : "l"(g_ll + i));
                s += x;
            }
            out[0] = -s / (float)BB;
            g_done = 0;                    // reset for next replay
        }
    }
}

extern "C" void kernel_launch(void* const* d_in, const int* in_sizes, int n_in,
                              void* d_out, int out_size) {
    const float* acts       = (const float*)d_in[0];
    const int*   labels     = (const int*)d_in[1];
    const int*   act_lens   = (const int*)d_in[2];
    const int*   label_lens = (const int*)d_in[3];
    float* out = (float*)d_out;

    const int lse_blocks = (BB * TT * UU) / 8;     // 16640
    rnnt_fused<<<8 + lse_blocks, 256>>>(acts, labels, act_lens, label_lens, out);
}

// round 8
// speedup vs baseline: 1.4166x; 1.4166x over previous
#include <cuda_runtime.h>
#include <cuda_bf16.h>
#include <math.h>

#define BB 8
#define TT 256
#define UU 65
#define UL 64
#define VV 1024
#define ND 320             // stored diagonals t+u in [0,319]
#define ST 66              // diag row stride (floats), even -> 8B-aligned float2
#define CT 64              // t-rows per lse chunk
#define NEG_BIG (-1e30f)
#define LOG2E 1.4426950408889634f
#define LN2F  0.6931471805599453f

__device__ __align__(16) float g_blankD[BB * ND * ST];  // [b][t+u][u] = lp_blank*log2e
__device__ __align__(16) float g_labelD[BB * ND * ST];  // [b][t+u][u] = lp_label*log2e
__device__ __align__(16) float g_state[BB * 32 * 4];    // a0,a1,a2,tgt per lane
__device__ float g_ll[BB];
__device__ int   g_done;

__device__ __forceinline__ float warpMax(float v) {
#pragma unroll
    for (int o = 16; o > 0; o >>= 1) v = fmaxf(v, __shfl_xor_sync(0xffffffffu, v, o));
    return v;
}
__device__ __forceinline__ float warpSum(float v) {
#pragma unroll
    for (int o = 16; o > 0; o >>= 1) v += __shfl_xor_sync(0xffffffffu, v, o);
    return v;
}
__device__ __forceinline__ float lae2(float a, float b) {   // logaddexp in log2 domain
    float m = fmaxf(a, b);
    float d = fminf(a, b) - m;
    float p, r;
    asm("ex2.approx.ftz.f32 %0, %1;" : "=f"(p) : "f"(d));
    float q = 1.f + p;
    asm("lg2.approx.ftz.f32 %0, %1;" : "=f"(r) : "f"(q));
    return m + r;
}

struct Ops { float bx, by, b64, lx, ly; };

// One step of the pipeline. bids [0,8) = alpha chunk (warp 0 only);
// bids [8, 8+4160) = lse for t in [t_base, t_base+64). No smem, no fences:
// alpha only reads data written by PREVIOUS launches.
__global__ void __launch_bounds__(256) rnnt_step(const float* __restrict__ acts,
                                                 const int* __restrict__ labels,
                                                 const int* __restrict__ act_lens,
                                                 const int* __restrict__ label_lens,
                                                 float* __restrict__ out,
                                                 int t_base, int dlo, int dhi) {
    const int lane = threadIdx.x & 31;
    const int wid  = threadIdx.x >> 5;

    if (blockIdx.x >= 8) {
        // ===================== LSE producer (R6 body, diag-major store) ======
        const int sched = (blockIdx.x - 8) * 8 + wid;   // 0 .. 33279
        const int b   = sched / (CT * UU);
        const int rem = sched - b * (CT * UU);
        const int t   = t_base + rem / UU;
        const int u   = rem - (rem / UU) * UU;
        const int row = (b * TT + t) * UU + u;

        const float4* a4 = reinterpret_cast<const float4*>(acts + (size_t)row * VV);
        float4 v[8];
#pragma unroll
        for (int j = 0; j < 8; ++j) v[j] = a4[lane + 32 * j];

        float m = -INFINITY;
#pragma unroll
        for (int j = 0; j < 8; ++j)
            m = fmaxf(m, fmaxf(fmaxf(v[j].x, v[j].y), fmaxf(v[j].z, v[j].w)));
        m = warpMax(m);

        float s = 0.f;
#pragma unroll
        for (int j = 0; j < 8; ++j)
            s += __expf(v[j].x - m) + __expf(v[j].y - m) + __expf(v[j].z - m) + __expf(v[j].w - m);
        s = warpSum(s);
        const float lse = m + __logf(s);

        float lv = 0.f;
        if (u < UL) {
            const int lab = labels[b * UL + u];
            const int q = lab >> 2, c = lab & 3, jj = q >> 5;
            float cand = 0.f;
#pragma unroll
            for (int j = 0; j < 8; ++j) {
                if (j == jj) {
                    float4 f = v[j];
                    cand = (c == 0) ? f.x : (c == 1) ? f.y : (c == 2) ? f.z : f.w;
                }
            }
            lv = __shfl_sync(0xffffffffu, cand, q & 31);
        }
        if (lane == 0) {
            const size_t base = ((size_t)b * ND + (t + u)) * ST + u;
            g_blankD[base] = (v[0].x - lse) * LOG2E;
            if (u < UL) g_labelD[base] = (lv - lse) * LOG2E;
        }
        return;
    }

    // ===================== ALPHA chunk: one warp per batch ===================
    if (wid != 0 || dhi < dlo) return;
    const int b = blockIdx.x;

    const int t_tgt = act_lens[b] - 1;
    const int u_tgt = label_lens[b];
    const int d_tgt = t_tgt + u_tgt;

    const float* BD = g_blankD + (size_t)b * ND * ST;
    const float* LD = g_labelD + (size_t)b * ND * ST;
    const int u0 = 2 * lane, u1 = u0 + 1;

    auto loadOps = [&](int d) {
        const int dd = min(d - 1, ND - 1);
        const float* bp = BD + (size_t)dd * ST;
        const float* lp = LD + (size_t)dd * ST;
        Ops o;
        const float2 bv = *reinterpret_cast<const float2*>(bp + u0);
        const float2 lv = *reinterpret_cast<const float2*>(lp + u0);
        o.bx = bv.x; o.by = bv.y; o.lx = lv.x; o.ly = lv.y;
        o.b64 = bp[64];
        return o;
    };

    float a0 = 0.f, a1 = 0.f, a2 = 0.f, tgt = 0.f;
    if (dlo > 1) {
        const float4 st4 = *reinterpret_cast<const float4*>(g_state + (b * 32 + lane) * 4);
        a0 = st4.x; a1 = st4.y; a2 = st4.z; tgt = st4.w;
    }

    Ops oA = loadOps(dlo), oB = loadOps(dlo + 1), oC = loadOps(dlo + 2);

#pragma unroll 2
    for (int d = dlo; d <= dhi; ++d) {
        Ops oD = loadOps(d + 3);                         // depth-3 prefetch

        const float l_m1 = __shfl_up_sync(0xffffffffu, oA.ly, 1);  // label col u0-1
        const float l_63 = __shfl_sync(0xffffffffu, oA.ly, 31);    // label col 63
        float pm = __shfl_up_sync(0xffffffffu, a1, 1);
        pm = (lane == 0) ? NEG_BIG : pm;

        const int t0 = d - u0, t1 = t0 - 1, t2 = d - 64;

        const float bl0 = (t0 >= 1) ? oA.bx : NEG_BIG;
        const float n0  = lae2(a0 + bl0, pm + l_m1);

        const float bl1 = (t1 >= 1) ? oA.by : NEG_BIG;
        const float n1  = lae2(a1 + bl1, a0 + oA.lx);

        const float bl2 = (t2 >= 1) ? oA.b64 : NEG_BIG;
        const float n2  = lae2(a2 + bl2, a1 + l_63);

        a0 = (t0 >= 0 && t0 < TT) ? n0 : a0;
        a1 = (t1 >= 0 && t1 < TT) ? n1 : a1;
        a2 = (t2 >= 0 && t2 < TT) ? n2 : a2;

        const float pick = (u_tgt == u0) ? n0 : ((u_tgt == u1) ? n1 : n2);
        tgt = (d == d_tgt) ? pick : tgt;

        oA = oB; oB = oC; oC = oD;
    }

    if (dhi < TT + UU - 2) {
        float4 st4; st4.x = a0; st4.y = a1; st4.z = a2; st4.w = tgt;
        *reinterpret_cast<float4*>(g_state + (b * 32 + lane) * 4) = st4;
        return;
    }

    // final chunk: epilogue + deterministic finalize (R6-proven ticket)
    const int owner = (u_tgt >= 64) ? 31 : (u_tgt >> 1);
    const float av = __shfl_sync(0xffffffffu, tgt, owner);
    if (lane == 0) {
        const float bl = BD[(size_t)d_tgt * ST + u_tgt];   // already log2e-scaled
        g_ll[b] = (av + bl) * LN2F;
        __threadfence();
        const int old = atomicAdd(&g_done, 1);
        if (old == BB - 1) {
            float s = 0.f;
#pragma unroll
            for (int i = 0; i < BB; ++i) s += g_ll[i];
            out[0] = -s / (float)BB;
            g_done = 0;                    // reset for next graph replay
            __threadfence();
        }
    }
}

extern "C" void kernel_launch(void* const* d_in, const int* in_sizes, int n_in,
                              void* d_out, int out_size) {
    const float* acts       = (const float*)d_in[0];
    const int*   labels     = (const int*)d_in[1];
    const int*   act_lens   = (const int*)d_in[2];
    const int*   label_lens = (const int*)d_in[3];
    float* out = (float*)d_out;

    const int lse_blocks = (BB * CT * UU) / 8;     // 4160
    const int full = 8 + lse_blocks;

    // L0: lse t[0,64)                       (no alpha)
    rnnt_step<<<full, 256>>>(acts, labels, act_lens, label_lens, out,   0, 1, 0);
    // L1: lse t[64,128)  + alpha d 1..64    (needs t<=63: done in L0)
    rnnt_step<<<full, 256>>>(acts, labels, act_lens, label_lens, out,  64, 1, 64);
    // L2: lse t[128,192) + alpha d 65..128  (needs t<=127)
    rnnt_step<<<full, 256>>>(acts, labels, act_lens, label_lens, out, 128, 65, 128);
    // L3: lse t[192,256) + alpha d 129..192 (needs t<=191)
    rnnt_step<<<full, 256>>>(acts, labels, act_lens, label_lens, out, 192, 129, 192);
    // L4: alpha d 193..319 + finalize
    rnnt_step<<<8, 256>>>(acts, labels, act_lens, label_lens, out, 0, 193, 319);
}